// round 1
// baseline (speedup 1.0000x reference)
#include <cuda_runtime.h>
#include <math.h>

#define BATCH 4
#define LQ 257        // NTOK+1
#define DMODEL 384
#define DIN 768
#define NST 16
#define DTR 24
#define KCONV 4
#define NTOK 256
#define POSI 128
#define BL (BATCH*LQ)   // 1028

// ------------------ scratch (no allocations allowed) ------------------
__device__ float g_xr[BATCH*NTOK*256];
__device__ float g_tok[BATCH*NTOK*DMODEL];
__device__ float g_resid[BL*DMODEL];
__device__ float g_hidden[BL*DMODEL];
__device__ float g_hln[BL*DMODEL];
__device__ float g_xz[BL*2*DIN];
__device__ float g_xc[2][BL*DIN];
__device__ float g_dt[2][BL*DIN];
__device__ float g_bc[2][BL*2*NST];
__device__ float g_y[2][BL*DIN];
__device__ float g_ysum[BL*DIN];

// ------------------ patch gather ------------------
__global__ void k_gather(const float* __restrict__ depth) {
    int b = blockIdx.y, p = blockIdx.x, t = threadIdx.x;     // t < 256
    int i = t >> 4, j = t & 15;
    int gh = p >> 3, gw = p & 7;
    int row = gh * 16 + i;               // 0..511
    int tt = row >> 7, hh = row & 127;
    int col = gw * 16 + j;
    g_xr[((b * NTOK + p) << 8) + t] =
        depth[(((b * 4 + tt) << 7) + hh) * 128 + col];
}

// ------------------ assemble tokens + cls + pos ------------------
__global__ void k_assemble(const float* __restrict__ cls,
                           const float* __restrict__ pos,
                           const float* __restrict__ pb) {
    int b = blockIdx.y, l = blockIdx.x, d = threadIdx.x;   // d < 384
    float v;
    if (l == POSI) v = cls[d];
    else {
        int p = (l < POSI) ? l : (l - 1);
        v = g_tok[(b * NTOK + p) * DMODEL + d] + pb[d];
    }
    g_resid[(b * LQ + l) * DMODEL + d] = v + pos[l * DMODEL + d];
}

// ------------------ residual add + layernorm ------------------
__global__ void k_lnadd(int add, const float* __restrict__ w,
                        const float* __restrict__ bb) {
    int row = blockIdx.x;         // 0..BL-1
    int tid = threadIdx.x;        // 128 threads
    __shared__ float red[4];
    float* rp = g_resid + (size_t)row * DMODEL;
    float loc[3];
    float s = 0.f;
#pragma unroll
    for (int q = 0; q < 3; q++) {
        int d = tid + 128 * q;
        float v = rp[d];
        if (add) { v += g_hidden[(size_t)row * DMODEL + d]; rp[d] = v; }
        loc[q] = v; s += v;
    }
    for (int m = 16; m; m >>= 1) s += __shfl_down_sync(0xffffffffu, s, m);
    if ((tid & 31) == 0) red[tid >> 5] = s;
    __syncthreads();
    float mean = (red[0] + red[1] + red[2] + red[3]) * (1.0f / DMODEL);
    float vs = 0.f;
#pragma unroll
    for (int q = 0; q < 3; q++) { float dv = loc[q] - mean; vs += dv * dv; }
    __syncthreads();
    for (int m = 16; m; m >>= 1) vs += __shfl_down_sync(0xffffffffu, vs, m);
    if ((tid & 31) == 0) red[tid >> 5] = vs;
    __syncthreads();
    float var = (red[0] + red[1] + red[2] + red[3]) * (1.0f / DMODEL);
    float rstd = rsqrtf(var + 1e-5f);
#pragma unroll
    for (int q = 0; q < 3; q++) {
        int d = tid + 128 * q;
        g_hln[(size_t)row * DMODEL + d] = (loc[q] - mean) * rstd * w[d] + bb[d];
    }
}

// ------------------ generic SGEMM: C[M,N] = A[M,K] * B[N,K]^T ------------------
__global__ void k_sgemm(const float* __restrict__ A, const float* __restrict__ B,
                        float* __restrict__ C, int M, int Nn, int K) {
    const int BM = 64, BN = 64, BK = 16;
    __shared__ float As[BK][BM + 1];
    __shared__ float Bs[BK][BN + 1];
    int tid = threadIdx.x;                 // 256
    int tx = tid & 15, ty = tid >> 4;
    int m0 = blockIdx.y * BM, n0 = blockIdx.x * BN;
    int lrow = tid >> 2;                   // 0..63
    int lc = (tid & 3) << 2;               // 0,4,8,12
    float acc[4][4] = {};
    for (int k0 = 0; k0 < K; k0 += BK) {
        float4 av = make_float4(0.f, 0.f, 0.f, 0.f);
        float4 bv = make_float4(0.f, 0.f, 0.f, 0.f);
        int am = m0 + lrow;
        if (am < M)
            av = *reinterpret_cast<const float4*>(&A[(size_t)am * K + k0 + lc]);
        int bn = n0 + lrow;
        if (bn < Nn)
            bv = *reinterpret_cast<const float4*>(&B[(size_t)bn * K + k0 + lc]);
        As[lc + 0][lrow] = av.x; As[lc + 1][lrow] = av.y;
        As[lc + 2][lrow] = av.z; As[lc + 3][lrow] = av.w;
        Bs[lc + 0][lrow] = bv.x; Bs[lc + 1][lrow] = bv.y;
        Bs[lc + 2][lrow] = bv.z; Bs[lc + 3][lrow] = bv.w;
        __syncthreads();
#pragma unroll
        for (int kk = 0; kk < BK; kk++) {
            float a[4], bw[4];
#pragma unroll
            for (int i = 0; i < 4; i++) a[i] = As[kk][ty * 4 + i];
#pragma unroll
            for (int j = 0; j < 4; j++) bw[j] = Bs[kk][tx * 4 + j];
#pragma unroll
            for (int i = 0; i < 4; i++)
#pragma unroll
                for (int j = 0; j < 4; j++) acc[i][j] += a[i] * bw[j];
        }
        __syncthreads();
    }
#pragma unroll
    for (int i = 0; i < 4; i++) {
        int m = m0 + ty * 4 + i;
        if (m >= M) continue;
#pragma unroll
        for (int j = 0; j < 4; j++) {
            int n = n0 + tx * 4 + j;
            if (n < Nn) C[(size_t)m * Nn + n] = acc[i][j];
        }
    }
}

// ------------------ causal conv + silu (both directions) ------------------
__global__ void k_conv(const float* __restrict__ cwf, const float* __restrict__ cbf,
                       const float* __restrict__ cwb, const float* __restrict__ cbb) {
    int l = blockIdx.x, b = blockIdx.y, br = blockIdx.z;
    int d = threadIdx.x;                       // 768
    const float* w = (br ? cwb : cwf) + d * KCONV;
    float acc = (br ? cbb : cbf)[d];
#pragma unroll
    for (int k = 0; k < KCONV; k++) {
        int idx = l - 3 + k;
        if (idx >= 0) {
            int src = br ? (NTOK - idx) : idx;       // flip for backward branch
            acc += w[k] * g_xz[((size_t)(b * LQ + src)) * (2 * DIN) + d];
        }
    }
    float s = acc / (1.f + __expf(-acc));
    g_xc[br][(size_t)(b * LQ + l) * DIN + d] = s;
}

// ------------------ xproj (dt_raw,B,C) + dtproj + softplus, fused ------------------
__global__ void k_xprojdt(const float* __restrict__ xwf, const float* __restrict__ xwb,
                          const float* __restrict__ dwf, const float* __restrict__ dbf,
                          const float* __restrict__ dwb, const float* __restrict__ dbb) {
    int l = blockIdx.x, b = blockIdx.y, br = blockIdx.z;
    int tid = threadIdx.x;                  // 256
    __shared__ float sx[DIN];
    __shared__ float sdb[56];
    const float* xcrow = &g_xc[br][(size_t)(b * LQ + l) * DIN];
    for (int d = tid; d < DIN; d += 256) sx[d] = xcrow[d];
    __syncthreads();
    const float* xw = br ? xwb : xwf;
    int w = tid >> 5, lane = tid & 31;
#pragma unroll
    for (int q = 0; q < 7; q++) {
        int e = w + (q << 3);               // 8 warps x 7 = 56 outputs
        const float* wr = xw + (size_t)e * DIN;
        float p = 0.f;
        for (int dd = lane; dd < DIN; dd += 32) p += sx[dd] * wr[dd];
        for (int m = 16; m; m >>= 1) p += __shfl_down_sync(0xffffffffu, p, m);
        if (lane == 0) sdb[e] = p;
    }
    __syncthreads();
    if (tid < 32)
        g_bc[br][(size_t)(b * LQ + l) * 32 + tid] = sdb[24 + tid];
    const float* dw = br ? dwb : dwf;
    const float* db = br ? dbb : dbf;
#pragma unroll
    for (int q = 0; q < 3; q++) {
        int d = tid + (q << 8);
        float acc = db[d];
        const float* dr = dw + (size_t)d * DTR;
#pragma unroll
        for (int r = 0; r < DTR; r++) acc += sdb[r] * dr[r];
        float sp = (acc > 20.f) ? acc : log1pf(__expf(acc));
        g_dt[br][(size_t)(b * LQ + l) * DIN + d] = sp;
    }
}

// ------------------ selective scan: thread per (d,n), shuffle-reduce over n ------------------
__global__ void k_ssm(const float* __restrict__ Alf, const float* __restrict__ Alb,
                      const float* __restrict__ Dpf, const float* __restrict__ Dpb) {
    int chunk = blockIdx.x;            // 0..47  (DIN/16)
    int b = blockIdx.y, br = blockIdx.z;
    int tid = threadIdx.x;             // 256 = 16 d x 16 n
    int n = tid & 15, dl = tid >> 4;
    int d = chunk * 16 + dl;
    const float* Al = br ? Alb : Alf;
    float A = -__expf(Al[(size_t)d * NST + n]);
    float Dv = (br ? Dpb : Dpf)[d];
    const float* dtb = g_dt[br] + (size_t)b * LQ * DIN;
    const float* xcb = g_xc[br] + (size_t)b * LQ * DIN;
    const float* bcb = g_bc[br] + (size_t)b * LQ * 2 * NST;
    float* yb = g_y[br] + (size_t)b * LQ * DIN;
    float h = 0.f;
    for (int t = 0; t < LQ; t++) {
        float dtv = dtb[(size_t)t * DIN + d];
        float xv  = xcb[(size_t)t * DIN + d];
        float Bn  = bcb[t * 32 + n];
        float Cn  = bcb[t * 32 + 16 + n];
        float dA = __expf(dtv * A);
        h = dA * h + dtv * Bn * xv;
        float p = h * Cn;
        p += __shfl_xor_sync(0xffffffffu, p, 8);
        p += __shfl_xor_sync(0xffffffffu, p, 4);
        p += __shfl_xor_sync(0xffffffffu, p, 2);
        p += __shfl_xor_sync(0xffffffffu, p, 1);
        if (n == 0) {
            int zl = br ? (NTOK - t) : t;   // z is flipped for backward branch
            float zv = g_xz[(size_t)(b * LQ + zl) * (2 * DIN) + DIN + d];
            float y = (p + xv * Dv) * (zv / (1.f + __expf(-zv)));
            yb[(size_t)t * DIN + d] = y;
        }
    }
}

// ------------------ combine forward + flipped backward ------------------
__global__ void k_combine() {
    int l = blockIdx.x, b = blockIdx.y, d = threadIdx.x;   // 768
    g_ysum[(size_t)(b * LQ + l) * DIN + d] =
        g_y[0][(size_t)(b * LQ + l) * DIN + d] +
        g_y[1][(size_t)(b * LQ + (NTOK - l)) * DIN + d];
}

// ------------------ final residual + LN + cmd MLP head ------------------
__global__ void k_final(const float* __restrict__ sv, const float* __restrict__ av,
                        const float* __restrict__ lnw, const float* __restrict__ lnb,
                        const float* __restrict__ cw1, const float* __restrict__ cb1,
                        const float* __restrict__ cw2, const float* __restrict__ cb2,
                        float* __restrict__ out) {
    int b = blockIdx.x, tid = threadIdx.x;   // 384 threads
    __shared__ float c1[DMODEL];
    __shared__ float cmdv[20];
    __shared__ float red[12];
    int row = b * LQ + POSI;
    float x = g_resid[(size_t)row * DMODEL + tid] + g_hidden[(size_t)row * DMODEL + tid];
    float s = x;
    for (int m = 16; m; m >>= 1) s += __shfl_down_sync(0xffffffffu, s, m);
    if ((tid & 31) == 0) red[tid >> 5] = s;
    __syncthreads();
    float tot = 0.f;
#pragma unroll
    for (int i = 0; i < 12; i++) tot += red[i];
    float mean = tot * (1.0f / DMODEL);
    float dv = x - mean;
    float vsq = dv * dv;
    __syncthreads();
    for (int m = 16; m; m >>= 1) vsq += __shfl_down_sync(0xffffffffu, vsq, m);
    if ((tid & 31) == 0) red[tid >> 5] = vsq;
    __syncthreads();
    float vt = 0.f;
#pragma unroll
    for (int i = 0; i < 12; i++) vt += red[i];
    float vis = dv * rsqrtf(vt * (1.0f / DMODEL) + 1e-5f) * lnw[tid] + lnb[tid];
    if (tid < 20) cmdv[tid] = (tid < 16) ? sv[b * 16 + tid] : av[b * 4 + tid - 16];
    __syncthreads();
    float a1 = cb1[tid];
#pragma unroll
    for (int k = 0; k < 20; k++) a1 += cmdv[k] * cw1[tid * 20 + k];
    c1[tid] = fmaxf(a1, 0.f);
    __syncthreads();
    float o = cb2[tid];
    for (int j = 0; j < DMODEL; j++) o += c1[j] * cw2[tid * DMODEL + j];
    out[b * DMODEL + tid] = vis + o;
}

// ------------------ host ------------------
extern "C" void kernel_launch(void* const* d_in, const int* in_sizes, int n_in,
                              void* d_out, int out_size) {
    const float* depth  = (const float*)d_in[0];
    const float* state  = (const float*)d_in[1];
    const float* action = (const float*)d_in[2];
    const float* patchw = (const float*)d_in[3];
    const float* patchb = (const float*)d_in[4];
    const float* cls    = (const float*)d_in[5];
    const float* pos    = (const float*)d_in[6];
    const float* lnw    = (const float*)d_in[7];
    const float* lnb    = (const float*)d_in[8];
    const float* inpw   = (const float*)d_in[9];
    const float* convw  = (const float*)d_in[10];
    const float* convb  = (const float*)d_in[11];
    const float* convwb = (const float*)d_in[12];
    const float* convbb = (const float*)d_in[13];
    const float* xpw    = (const float*)d_in[14];
    const float* xpwb   = (const float*)d_in[15];
    const float* dtw    = (const float*)d_in[16];
    const float* dtbv   = (const float*)d_in[17];
    const float* dtwb   = (const float*)d_in[18];
    const float* dtbb   = (const float*)d_in[19];
    const float* Alog   = (const float*)d_in[20];
    const float* Alogb  = (const float*)d_in[21];
    const float* Dp     = (const float*)d_in[22];
    const float* Dpb    = (const float*)d_in[23];
    const float* outw   = (const float*)d_in[24];
    const float* lnfw   = (const float*)d_in[25];
    const float* lnfb   = (const float*)d_in[26];
    const float* cw1    = (const float*)d_in[27];
    const float* cb1    = (const float*)d_in[28];
    const float* cw2    = (const float*)d_in[29];
    const float* cb2    = (const float*)d_in[30];

    float *p_xr, *p_tok, *p_hln, *p_xz, *p_ysum, *p_hidden;
    cudaGetSymbolAddress((void**)&p_xr, g_xr);
    cudaGetSymbolAddress((void**)&p_tok, g_tok);
    cudaGetSymbolAddress((void**)&p_hln, g_hln);
    cudaGetSymbolAddress((void**)&p_xz, g_xz);
    cudaGetSymbolAddress((void**)&p_ysum, g_ysum);
    cudaGetSymbolAddress((void**)&p_hidden, g_hidden);

    // patch embed
    k_gather<<<dim3(NTOK, BATCH), 256>>>(depth);
    k_sgemm<<<dim3((DMODEL + 63) / 64, (BATCH * NTOK + 63) / 64), 256>>>(
        p_xr, patchw, p_tok, BATCH * NTOK, DMODEL, 256);
    k_assemble<<<dim3(LQ, BATCH), DMODEL>>>(cls, pos, patchb);

    for (int i = 0; i < 4; i++) {
        k_lnadd<<<BL, 128>>>(i > 0, lnw + i * DMODEL, lnb + i * DMODEL);
        k_sgemm<<<dim3((2 * DIN + 63) / 64, (BL + 63) / 64), 256>>>(
            p_hln, inpw + (size_t)i * 2 * DIN * DMODEL, p_xz, BL, 2 * DIN, DMODEL);
        k_conv<<<dim3(LQ, BATCH, 2), DIN>>>(
            convw + i * DIN * KCONV, convb + i * DIN,
            convwb + i * DIN * KCONV, convbb + i * DIN);
        k_xprojdt<<<dim3(LQ, BATCH, 2), 256>>>(
            xpw + (size_t)i * 56 * DIN, xpwb + (size_t)i * 56 * DIN,
            dtw + (size_t)i * DIN * DTR, dtbv + i * DIN,
            dtwb + (size_t)i * DIN * DTR, dtbb + i * DIN);
        k_ssm<<<dim3(DIN / 16, BATCH, 2), 256>>>(
            Alog + (size_t)i * DIN * NST, Alogb + (size_t)i * DIN * NST,
            Dp + i * DIN, Dpb + i * DIN);
        k_combine<<<dim3(LQ, BATCH), DIN>>>();
        k_sgemm<<<dim3((DMODEL + 63) / 64, (BL + 63) / 64), 256>>>(
            p_ysum, outw + (size_t)i * DMODEL * DIN, p_hidden, BL, DMODEL, DIN);
    }

    k_final<<<BATCH, DMODEL>>>(state, action, lnfw, lnfb, cw1, cb1, cw2, cb2,
                               (float*)d_out);
}